// round 13
// baseline (speedup 1.0000x reference)
#include <cuda_runtime.h>
#include <cstdint>

#define CCH 128
#define KK3 27
#define SAF 132                         // A smem row stride (floats) — conflict-free A frags
#define SBF 136                         // B smem row stride (floats) — conflict-free B frags
#define SMEM_DYN (2 * 128 * SAF * 4 + 128 * SBF * 4)   // 204800 B -> 1 CTA/SM

__device__ float g_sum[CCH];
__device__ float g_sqs[CCH];

static __device__ __forceinline__ float to_tf32(float x) {
    float r; asm("cvt.rna.tf32.f32 %0, %1;" : "=f"(r) : "f"(x)); return r;
}

static __device__ __forceinline__ void mma8(float* c, const uint32_t* a,
                                            uint32_t b0, uint32_t b1) {
    asm volatile(
        "mma.sync.aligned.m16n8k8.row.col.f32.tf32.tf32.f32 "
        "{%0,%1,%2,%3}, {%4,%5,%6,%7}, {%8,%9}, {%0,%1,%2,%3};"
        : "+f"(c[0]), "+f"(c[1]), "+f"(c[2]), "+f"(c[3])
        : "r"(a[0]), "r"(a[1]), "r"(a[2]), "r"(a[3]), "r"(b0), "r"(b1));
}

// Gather 128x128 f32 tile into smem (stride SAF). OOB rows -> 0. tf32-rounded.
static __device__ __forceinline__ void gather_tile(float* __restrict__ As,
                                                   const float* __restrict__ feats,
                                                   const int* __restrict__ imk,
                                                   int tb, int Mtot, int tid) {
#pragma unroll
    for (int p = 0; p < 8; ++p) {
        int lin = (p << 9) + tid;
        int row = lin >> 5, q = lin & 31;
        int gm  = tb + row;
        float4 v = make_float4(0.f, 0.f, 0.f, 0.f);
        if (gm < Mtot) {
            int g = __ldg(imk + gm);
            v = __ldg(reinterpret_cast<const float4*>(feats) + ((size_t)g << 5) + q);
            v.x = to_tf32(v.x); v.y = to_tf32(v.y);
            v.z = to_tf32(v.z); v.w = to_tf32(v.w);
        }
        *reinterpret_cast<float4*>(&As[row * SAF + (q << 2)]) = v;
    }
}

// One scatter unit u=0..7 (mt=u>>2, nt=u&3): butterfly-assemble a float4 of one
// output row from the C-fragment quad, then fire a no-return red.global.add.v4.
static __device__ __forceinline__ void scatter_unit(const float (&prv)[2][4][4],
                                                    float* const (&pp)[2],
                                                    int u, bool odd) {
    const int mt = u >> 2, nt = u & 3;
    float s0 = odd ? prv[mt][nt][0] : prv[mt][nt][2];
    float s1 = odd ? prv[mt][nt][1] : prv[mt][nt][3];
    float p0 = __shfl_xor_sync(0xFFFFFFFFu, s0, 1);
    float p1 = __shfl_xor_sync(0xFFFFFFFFu, s1, 1);
    float4 v = odd ? make_float4(p0, p1, prv[mt][nt][2], prv[mt][nt][3])
                   : make_float4(prv[mt][nt][0], prv[mt][nt][1], p0, p1);
    if (pp[mt])
        asm volatile("red.global.add.v4.f32 [%0], {%1,%2,%3,%4};" ::
                     "l"(pp[mt] + (nt << 3)),
                     "f"(v.x), "f"(v.y), "f"(v.z), "f"(v.w) : "memory");
}

// Process one tile: issue next gather, run 16 fully-unrolled mma K-steps into
// `cur`, and interleave the 8 scatter units of the PREVIOUS tile (regs `prv`,
// pointers `pp`) one per two K-steps. Saves this tile's out pointers into pp.
static __device__ __forceinline__ void do_tile(
    float (&cur)[2][4][4], float (&prv)[2][4][4], float* (&pp)[2], bool doScat,
    const float* __restrict__ Ac, const float* __restrict__ Bs,
    float* __restrict__ An, const float* __restrict__ feats,
    const int* __restrict__ imk, int tb_next, bool hasNext,
    const int* __restrict__ omk, float* __restrict__ out, int tb, int Mtot,
    int tid, int gid, int tg, int warp_m, int warp_n, bool odd) {
    // New out-row pointers (issued early; latency hides under mma).
    float* np[2];
#pragma unroll
    for (int mt = 0; mt < 2; ++mt) {
        const int r  = (warp_m << 5) + (mt << 4) + gid + ((tg & 1) << 3);
        const int gm = tb + r;
        np[mt] = nullptr;
        if (gm < Mtot)
            np[mt] = out + (size_t)__ldg(omk + gm) * CCH
                   + (warp_n << 5) + ((tg & 2) << 1);
    }

    if (hasNext) gather_tile(An, feats, imk, tb_next, Mtot, tid);

#pragma unroll
    for (int mt = 0; mt < 2; ++mt)
#pragma unroll
        for (int nt = 0; nt < 4; ++nt)
#pragma unroll
            for (int e = 0; e < 4; ++e) cur[mt][nt][e] = 0.f;

#pragma unroll
    for (int ks = 0; ks < 16; ++ks) {
        const int kb = ks << 3;
        uint32_t a[2][4];
#pragma unroll
        for (int mt = 0; mt < 2; ++mt) {
            const int r = (warp_m << 5) + (mt << 4) + gid;
            a[mt][0] = __float_as_uint(Ac[r * SAF + kb + tg]);
            a[mt][1] = __float_as_uint(Ac[(r + 8) * SAF + kb + tg]);
            a[mt][2] = __float_as_uint(Ac[r * SAF + kb + tg + 4]);
            a[mt][3] = __float_as_uint(Ac[(r + 8) * SAF + kb + tg + 4]);
        }
#pragma unroll
        for (int nt = 0; nt < 4; ++nt) {
            const int cn = (warp_n << 5) + (nt << 3) + gid;
            uint32_t b0 = __float_as_uint(Bs[(kb + tg) * SBF + cn]);
            uint32_t b1 = __float_as_uint(Bs[(kb + tg + 4) * SBF + cn]);
            mma8(cur[0][nt], a[0], b0, b1);
            mma8(cur[1][nt], a[1], b0, b1);
        }
        if ((ks & 1) && doScat) scatter_unit(prv, pp, ks >> 1, odd);
    }
    pp[0] = np[0]; pp[1] = np[1];
}

// ---------------------------------------------------------------------------
// Persistent conv, software-pipelined: scatter(tile j-1) interleaves with
// mma(tile j); gather(tile j+1) issued ahead. One CTA barrier per tile.
// ---------------------------------------------------------------------------
__global__ void __launch_bounds__(512, 1)
conv_kernel(const float* __restrict__ feats, const float* __restrict__ Wmat,
            const int* __restrict__ in_maps, const int* __restrict__ out_maps,
            float* __restrict__ out, int Mtot) {
    extern __shared__ float sm[];
    float* const A0 = sm;
    float* const A1 = sm + 128 * SAF;
    float* const Bs = sm + 2 * 128 * SAF;

    const int tid  = threadIdx.x;
    const int wid  = tid >> 5;
    const int lane = tid & 31;
    const int gid  = lane >> 2;
    const int tg   = lane & 3;
    const int warp_m = wid & 3;
    const int warp_n = wid >> 2;
    const bool odd = (tg & 1);

    const int TPK   = (Mtot + 127) >> 7;
    const int total = KK3 * TPK;
    const int chunk = (total + gridDim.x - 1) / gridDim.x;
    int t = blockIdx.x * chunk;
    const int t1 = min(total, t + chunk);

    float accA[2][4][4], accB[2][4][4];
    float* pp[2] = {nullptr, nullptr};
    int cnt = 0;
    int ab  = 0;   // which A buffer holds the CURRENT tile's gathered data

    while (t < t1) {
        const int kk     = t / TPK;
        const int segEnd = min(t1, (kk + 1) * TPK);
        const int kt0    = kk * TPK;
        const int* imk   = in_maps  + (size_t)kk * Mtot;
        const int* omk   = out_maps + (size_t)kk * Mtot;
        const float4* Wk4 = reinterpret_cast<const float4*>(Wmat + (size_t)kk * (CCH * CCH));

        // B = W[k] as [k][n], stride SBF. (Previous tile's barrier guarantees
        // all prior mma reads of Bs are done.)
#pragma unroll
        for (int p = 0; p < 8; ++p) {
            int lin4 = (p << 9) + tid;
            int row  = lin4 >> 5, n4 = lin4 & 31;
            float4 v = __ldg(Wk4 + lin4);
            v.x = to_tf32(v.x); v.y = to_tf32(v.y);
            v.z = to_tf32(v.z); v.w = to_tf32(v.w);
            *reinterpret_cast<float4*>(&Bs[row * SBF + (n4 << 2)]) = v;
        }
        gather_tile(ab ? A1 : A0, feats, imk, (t - kt0) << 7, Mtot, tid);
        __syncthreads();

        for (int j = t; j < segEnd; ++j) {
            const int tb = (j - kt0) << 7;
            const bool hasNext = (j + 1 < segEnd);
            float* const Ac = ab ? A1 : A0;
            float* const An = ab ? A0 : A1;

            if (cnt & 1)
                do_tile(accB, accA, pp, cnt > 0, Ac, Bs, An, feats, imk,
                        (j + 1 - kt0) << 7, hasNext, omk, out, tb, Mtot,
                        tid, gid, tg, warp_m, warp_n, odd);
            else
                do_tile(accA, accB, pp, cnt > 0, Ac, Bs, An, feats, imk,
                        (j + 1 - kt0) << 7, hasNext, omk, out, tb, Mtot,
                        tid, gid, tg, warp_m, warp_n, odd);

            __syncthreads();   // An gather complete; Ac free for re-gather
            ab ^= 1; ++cnt;
        }
        t = segEnd;
    }

    // Drain: scatter the final tile (bank = parity of last processed tile).
    if (cnt > 0) {
        if ((cnt - 1) & 1) {
#pragma unroll
            for (int u = 0; u < 8; ++u) scatter_unit(accB, pp, u, odd);
        } else {
#pragma unroll
            for (int u = 0; u < 8; ++u) scatter_unit(accA, pp, u, odd);
        }
    }
}

__global__ void __launch_bounds__(256) zero_kernel(float4* __restrict__ o, int n4) {
    int i = blockIdx.x * blockDim.x + threadIdx.x;
    if (blockIdx.x == 0 && threadIdx.x < CCH) { g_sum[threadIdx.x] = 0.f; g_sqs[threadIdx.x] = 0.f; }
    for (; i < n4; i += gridDim.x * blockDim.x)
        o[i] = make_float4(0.f, 0.f, 0.f, 0.f);
}

__global__ void __launch_bounds__(256) stats_kernel(const float4* __restrict__ out4, int Nrows) {
    __shared__ float4 ss[256], sq[256];
    const int tid = threadIdx.x, c4 = tid & 31, rl = tid >> 5;
    float4 s = make_float4(0.f, 0.f, 0.f, 0.f), q = s;
    for (int r = blockIdx.x * 8 + rl; r < Nrows; r += gridDim.x * 8) {
        float4 v = __ldg(out4 + (size_t)r * 32 + c4);
        s.x += v.x; s.y += v.y; s.z += v.z; s.w += v.w;
        q.x += v.x * v.x; q.y += v.y * v.y; q.z += v.z * v.z; q.w += v.w * v.w;
    }
    ss[tid] = s; sq[tid] = q;
    __syncthreads();
    if (rl == 0) {
#pragma unroll
        for (int j = 1; j < 8; ++j) {
            float4 a = ss[c4 + (j << 5)], b = sq[c4 + (j << 5)];
            s.x += a.x; s.y += a.y; s.z += a.z; s.w += a.w;
            q.x += b.x; q.y += b.y; q.z += b.z; q.w += b.w;
        }
        const int c = c4 << 2;
        atomicAdd(&g_sum[c + 0], s.x); atomicAdd(&g_sum[c + 1], s.y);
        atomicAdd(&g_sum[c + 2], s.z); atomicAdd(&g_sum[c + 3], s.w);
        atomicAdd(&g_sqs[c + 0], q.x); atomicAdd(&g_sqs[c + 1], q.y);
        atomicAdd(&g_sqs[c + 2], q.z); atomicAdd(&g_sqs[c + 3], q.w);
    }
}

__global__ void __launch_bounds__(256) norm_kernel(float4* __restrict__ out4,
                                                   const float* __restrict__ gamma,
                                                   const float* __restrict__ beta, int Nrows) {
    const int tid = threadIdx.x, c4 = tid & 31, rl = tid >> 5;
    const float invN = 1.0f / (float)Nrows;
    const int c = c4 << 2;
    float4 A, B;
    {
        float m0 = g_sum[c + 0] * invN, m1 = g_sum[c + 1] * invN;
        float m2 = g_sum[c + 2] * invN, m3 = g_sum[c + 3] * invN;
        A.x = rsqrtf(fmaxf(g_sqs[c + 0] * invN - m0 * m0, 0.f) + 1e-5f) * __ldg(gamma + c + 0);
        A.y = rsqrtf(fmaxf(g_sqs[c + 1] * invN - m1 * m1, 0.f) + 1e-5f) * __ldg(gamma + c + 1);
        A.z = rsqrtf(fmaxf(g_sqs[c + 2] * invN - m2 * m2, 0.f) + 1e-5f) * __ldg(gamma + c + 2);
        A.w = rsqrtf(fmaxf(g_sqs[c + 3] * invN - m3 * m3, 0.f) + 1e-5f) * __ldg(gamma + c + 3);
        B.x = __ldg(beta + c + 0) - m0 * A.x;
        B.y = __ldg(beta + c + 1) - m1 * A.y;
        B.z = __ldg(beta + c + 2) - m2 * A.z;
        B.w = __ldg(beta + c + 3) - m3 * A.w;
    }
    for (int r = blockIdx.x * 8 + rl; r < Nrows; r += gridDim.x * 8) {
        const size_t idx = (size_t)r * 32 + c4;
        float4 v = out4[idx];
        v.x = fmaf(v.x, A.x, B.x); v.y = fmaf(v.y, A.y, B.y);
        v.z = fmaf(v.z, A.z, B.z); v.w = fmaf(v.w, A.w, B.w);
        out4[idx] = v;
    }
}

extern "C" void kernel_launch(void* const* d_in, const int* in_sizes, int n_in,
                              void* d_out, int out_size) {
    const float* feats    = (const float*)d_in[0];
    const float* Wmat     = (const float*)d_in[1];
    const float* gamma    = (const float*)d_in[2];
    const float* beta     = (const float*)d_in[3];
    const int*   in_maps  = (const int*)d_in[4];
    const int*   out_maps = (const int*)d_in[5];
    float* out = (float*)d_out;

    const int Mtot  = in_sizes[4] / KK3;
    const int Nrows = out_size / CCH;

    cudaFuncSetAttribute(conv_kernel, cudaFuncAttributeMaxDynamicSharedMemorySize, SMEM_DYN);

    zero_kernel<<<2048, 256>>>((float4*)out, Nrows * (CCH / 4));
    conv_kernel<<<152, 512, SMEM_DYN>>>(feats, Wmat, in_maps, out_maps, out, Mtot);
    stats_kernel<<<1024, 256>>>((const float4*)out, Nrows);
    norm_kernel<<<1024, 256>>>((float4*)out, gamma, beta, Nrows);
}